// round 16
// baseline (speedup 1.0000x reference)
#include <cuda_runtime.h>
#include <cstdint>

// ---------------- problem constants ----------------
#define BB   16
#define DD   64
#define HH   768
#define NE   7
#define ROWS (BB*DD)                 // 1024 utterances
#define PAIRS_PER_B (DD*(DD+1)/2)    // 2080
#define NPAIR (BB*PAIRS_PER_B)       // 33280
#define FOLD_TASKS (2*1552)          // 3104
#define LUT_W  65                    // pair-LUT warps
#define PF_W   96                    // pooled-prefetch warps
#define PACK_ELEMS (8480 + HH)       // 9248: emo+G1+G2+gate-tail+zero-pad row

// ---------------- device scratch (no allocs allowed) ----------------
__device__ float g_Ob[4];             // folded expert bias [e*2+c]
__device__ float g_W19[20*HH];        // SoA packed weights [m][j], m=19 is a ZERO pad row
__device__ float g_Tail[12*8];        // tail weights for f=768..775: [m][f-768] over the 12 T columns
__device__ float g_T[ROWS*12];        // per-utterance table [G1(2) G2(2) O1(4) O2(4)]
__device__ float g_spk[ROWS];         // speaker ids as float
__device__ unsigned short g_pairidx[PAIRS_PER_B]; // packed (end<<8)|t per in-batch pair q
__device__ unsigned int g_cnt[BB];    // per-batch monotonic sync counters (never reset)

template<int N> __device__ __forceinline__ void cp_wait() {
    asm volatile("cp.async.wait_group %0;" :: "n"(N));
}

// ================= kernel A: fold + pack + spk + LUT + pooled L2 prefetch ===
__global__ void __launch_bounds__(256)
prep_kernel(const void*  __restrict__ spk_raw,
            const float* __restrict__ emo_w,
            const float* __restrict__ gate_w,
            const float* __restrict__ w1,
            const float* __restrict__ b1,
            const float* __restrict__ w2,
            const float* __restrict__ b2,
            const float* __restrict__ pooled) {
    const int gw   = (blockIdx.x * blockDim.x + threadIdx.x) >> 5;
    const int lane = threadIdx.x & 31;

    if (gw < FOLD_TASKS) {
        const int e = gw / 1552, j = gw - e * 1552;
        const float4* a4  = (const float4*)(w1 + ((size_t)(e * 1552 + j)) * 256);
        const float4* wb4 = (const float4*)(w2 + e * 512);
        float4 x0 = a4[lane];
        float4 x1 = a4[lane + 32];
        float4 p0 = wb4[2 * lane];
        float4 p1 = wb4[2 * lane + 1];
        float4 p2 = wb4[64 + 2 * lane];
        float4 p3 = wb4[65 + 2 * lane];
        float a0 = x0.x*p0.x + x0.y*p0.z + x0.z*p1.x + x0.w*p1.z
                 + x1.x*p2.x + x1.y*p2.z + x1.z*p3.x + x1.w*p3.z;
        float a1 = x0.x*p0.y + x0.y*p0.w + x0.z*p1.y + x0.w*p1.w
                 + x1.x*p2.y + x1.y*p2.w + x1.z*p3.y + x1.w*p3.w;
        #pragma unroll
        for (int off = 16; off; off >>= 1) {
            a0 += __shfl_down_sync(0xffffffffu, a0, off);
            a1 += __shfl_down_sync(0xffffffffu, a1, off);
        }
        if (lane == 0) {
            if (j < HH) {                          // first-half feature -> O1 (m = 11+e*2+c)
                g_W19[(11 + e * 2) * HH + j] = a0;
                g_W19[(12 + e * 2) * HH + j] = a1;
            } else if (j < 776) {                  // tail O1 feature: Tail m = 4+e*2+c
                g_Tail[(4 + e * 2) * 8 + (j - HH)] = a0;
                g_Tail[(5 + e * 2) * 8 + (j - HH)] = a1;
            } else if (j < 776 + HH) {             // second-half feature -> O2 (m = 15+e*2+c)
                int jj = j - 776;
                g_W19[(15 + e * 2) * HH + jj] = a0;
                g_W19[(16 + e * 2) * HH + jj] = a1;
            } else {                               // tail O2 feature: Tail m = 8+e*2+c
                g_Tail[(8 + e * 2) * 8 + (j - 776 - HH)] = a0;
                g_Tail[(9 + e * 2) * 8 + (j - 776 - HH)] = a1;
            }
        }
    } else if (gw < FOLD_TASKS + 4) {
        const int idx = gw - FOLD_TASKS;          // 0..3
        const int e = idx >> 1, c = idx & 1;
        float s = 0.f;
        for (int k = lane; k < 256; k += 32)
            s += b1[e * 256 + k] * w2[e * 512 + k * 2 + c];
        #pragma unroll
        for (int off = 16; off; off >>= 1)
            s += __shfl_down_sync(0xffffffffu, s, off);
        if (lane == 0) g_Ob[idx] = s + b2[e * 2 + c];
    } else if (gw == FOLD_TASKS + 4) {
        // speaker_ids stored int64 or int32 (values in {0,1}).
        // int64: odd 32-bit words of first 1024 words are all zero.
        const unsigned int* u = (const unsigned int*)spk_raw;
        unsigned nz = 0;
        for (int i = lane; i < ROWS; i += 32) nz |= u[2 * i + 1];
        unsigned any = __ballot_sync(0xffffffffu, nz != 0u);
        const bool w64 = (any == 0u);
        for (int i = lane; i < ROWS; i += 32)
            g_spk[i] = (float)(w64 ? u[2 * i] : u[i]);
    } else if (gw < FOLD_TASKS + 16) {
        // pack emo (5376) + G1 (1536) + G2 (1536) + gate tail (32)
        //    + zero pad row m=19 (768) = 9248 elems  (exact bound: OOB guard)
        const int pid = gw - (FOLD_TASKS + 5);    // 0..10
        for (int idx = pid * 32 + lane; idx < PACK_ELEMS; idx += 11 * 32) {
            if (idx < 5376) {
                int c = idx / HH, j = idx - c * HH;       // m = c
                g_W19[c * HH + j] = emo_w[j * 7 + c];
            } else if (idx < 5376 + 1536) {
                int q = idx - 5376;
                int c = q / HH, j = q - c * HH;           // m = 7+c
                g_W19[(7 + c) * HH + j] = gate_w[j * 2 + c];
            } else if (idx < 5376 + 3072) {
                int q = idx - 5376 - 1536;
                int c = q / HH, j = q - c * HH;           // m = 9+c
                g_W19[(9 + c) * HH + j] = gate_w[(776 + j) * 2 + c];
            } else if (idx < 5376 + 3072 + 32) {
                int q = idx - 5376 - 3072;                // 0..31
                int m = q >> 3, f8 = q & 7;
                int f = HH + f8;
                float v = (m < 2) ? gate_w[f * 2 + m]
                                  : gate_w[(776 + f) * 2 + (m - 2)];
                g_Tail[m * 8 + f8] = v;
            } else {
                int j = idx - 8480;                       // 0..767: zero pad row
                g_W19[19 * HH + j] = 0.f;
            }
        }
    } else if (gw < FOLD_TASKS + 16 + LUT_W) {
        // pair index LUT: q -> (end, t), end-major tril order
        const int q = (gw - (FOLD_TASKS + 16)) * 32 + lane;
        if (q < PAIRS_PER_B) {
            int end = (int)((sqrtf(8.f * (float)q + 1.f) - 1.f) * 0.5f);
            while ((end + 1) * (end + 2) / 2 <= q) end++;
            while (end * (end + 1) / 2 > q) end--;
            int t = q - end * (end + 1) / 2;
            g_pairidx[q] = (unsigned short)((end << 8) | t);
        }
    } else if (gw < FOLD_TASKS + 16 + LUT_W + PF_W) {
        // L2-prefetch the 3MB pooled matrix so solve's x staging hits L2.
        const int pw = gw - (FOLD_TASKS + 16 + LUT_W);    // 0..95
        const int lg = pw * 32 + lane;                    // 0..3071
        #pragma unroll
        for (int it = 0; it < 8; it++) {
            const float* addr = pooled + (size_t)(lg + 3072 * it) * 32; // 128B lines
            asm volatile("prefetch.global.L2 [%0];" :: "l"(addr));
        }
    }
}

// ================= kernel B: cp.async-pipelined x + 4-row weight reuse ======
// grid 128 x 256: block = 8 contiguous rows. x staged via cp.async in 6
// chunk-groups (chunk u = float4 cols [u*32,(u+1)*32) of all 8 rows, 4KB);
// compute of chunk u overlaps the DRAM transfer of chunks u+1..5.
// Warp w = (row-quad rq = w>>2, m-group mg = w&3; 5 m's incl. zero-pad m=19).
__global__ void __launch_bounds__(256, 2)
solve_kernel(const float* __restrict__ pooled,
             const float* __restrict__ emo_b,
             const float* __restrict__ gate_b,
             float* __restrict__ out_emo,     // [1024*7]
             float* __restrict__ out_cause) { // [33280*2]
    __shared__ float4 sx[8 * 192];            // 8 rows x 192 float4 = 24KB
    __shared__ float  spacc[8][20];           // [row_in_block][m] final sums

    const int tid  = threadIdx.x;
    const int lane = tid & 31;
    const int warp = tid >> 5;
    const int base = blockIdx.x * 8;          // first row of this block
    const int b    = blockIdx.x >> 3;         // batch
    const int s    = blockIdx.x & 7;          // pair slice

    // ---- issue all 6 staging chunks via cp.async (no dest registers) ----
    // thread (warp=row r, lane) copies float4 (r, u*32+lane) per chunk u.
    {
        const float4* src_row = (const float4*)pooled + (size_t)(base + warp) * 192;
        uint32_t dst_row = (uint32_t)__cvta_generic_to_shared(sx + warp * 192);
        #pragma unroll
        for (int u = 0; u < 6; u++) {
            uint32_t dst = dst_row + (uint32_t)(u * 32 + lane) * 16u;
            const float4* src = src_row + u * 32 + lane;
            asm volatile("cp.async.cg.shared.global [%0], [%1], 16;"
                         :: "r"(dst), "l"(src));
            asm volatile("cp.async.commit_group;");
        }
    }

    // ---- accumulate: warp = (row-quad, m-group), weights reused x4 rows ----
    const int rq = warp >> 2;                 // 0..1
    const int mg = warp & 3;                  // 0..3
    const int m0 = mg * 5;
    const float4* gW4 = (const float4*)g_W19;

    float acc[4][5];
    #pragma unroll
    for (int rr = 0; rr < 4; rr++)
        #pragma unroll
        for (int mm = 0; mm < 5; mm++) acc[rr][mm] = 0.f;

    auto do_chunk = [&](int u) {
        const int k = u * 32 + lane;          // float4 index 0..191
        float4 w[5];
        #pragma unroll
        for (int mm = 0; mm < 5; mm++)
            w[mm] = __ldg(gW4 + (m0 + mm) * 192 + k);
        #pragma unroll
        for (int rr = 0; rr < 4; rr++) {
            const float4 xv = sx[(rq * 4 + rr) * 192 + k];
            #pragma unroll
            for (int mm = 0; mm < 5; mm++)
                acc[rr][mm] += xv.x * w[mm].x + xv.y * w[mm].y
                             + xv.z * w[mm].z + xv.w * w[mm].w;
        }
    };

    cp_wait<5>(); __syncthreads(); do_chunk(0);
    cp_wait<4>(); __syncthreads(); do_chunk(1);
    cp_wait<3>(); __syncthreads(); do_chunk(2);
    cp_wait<2>(); __syncthreads(); do_chunk(3);
    cp_wait<1>(); __syncthreads(); do_chunk(4);
    cp_wait<0>(); __syncthreads(); do_chunk(5);

    // reduce 20 sums across the warp
    #pragma unroll
    for (int off = 16; off; off >>= 1) {
        #pragma unroll
        for (int rr = 0; rr < 4; rr++)
            #pragma unroll
            for (int mm = 0; mm < 5; mm++)
                acc[rr][mm] += __shfl_down_sync(0xffffffffu, acc[rr][mm], off);
    }
    if (lane == 0) {
        #pragma unroll
        for (int rr = 0; rr < 4; rr++)
            #pragma unroll
            for (int mm = 0; mm < 5; mm++)
                spacc[rq * 4 + rr][m0 + mm] = acc[rr][mm];
    }
    __syncthreads();

    // ---- finalize: warps 0-7, one row each, lanes = m (sums final) ----
    {
        const int row = warp;                 // 0..7
        const int i = base + row;
        float sacc = (lane < 19) ? spacc[row][lane] : 0.f;
        float ep = (lane < 7) ? sacc + emo_b[lane] : 0.f;

        // convergent broadcasts (all 32 lanes execute the same shfls)
        float epv[7];
        #pragma unroll
        for (int f8 = 0; f8 < 7; f8++)
            epv[f8] = __shfl_sync(0xffffffffu, ep, f8);

        if (lane < 7)
            out_emo[(size_t)i * 7 + lane] = ep;
        else if (lane < 19) {
            const int m = lane - 7;           // T column 0..11
            float v = sacc;
            #pragma unroll
            for (int f8 = 0; f8 < 7; f8++)
                v += epv[f8] * g_Tail[m * 8 + f8];
            v += g_spk[i] * g_Tail[m * 8 + 7];
            g_T[i * 12 + m] = v;
        }
    }

    // ---- per-batch sync (monotonic ticket; 8 blocks per counter) ----
    // 128 blocks <= 148 SMs -> entire grid wave-1 resident, spin is safe.
    __syncthreads();
    if (tid == 0) {
        __threadfence();
        unsigned t = atomicAdd(&g_cnt[b], 1u) + 1u;
        unsigned round_end = ((t + 7u) / 8u) * 8u;
        volatile unsigned int* c = &g_cnt[b];
        while (*c < round_end) { __nanosleep(32); }
        __threadfence();
    }
    __syncthreads();

    // ---- pair phase: 260 pairs per block, 2 pairs/thread, float4 stores ----
    if (tid < 130) {
        const float gb0 = gate_b[0];
        const float gb1 = gate_b[1];
        const float ob0 = g_Ob[0], ob1 = g_Ob[1], ob2 = g_Ob[2], ob3 = g_Ob[3];
        const float* Tb = g_T + b * DD * 12;

        const int q0 = s * 260 + tid * 2;     // even; q0,q0+1 within batch
        float4 res;
        {
            const unsigned pe = g_pairidx[q0];
            const float* Tt = Tb + (pe & 255) * 12;
            const float* Te = Tb + (pe >> 8) * 12;
            float g0 = Tt[0] + Te[2] + gb0;
            float g1 = Tt[1] + Te[3] + gb1;
            res.x = g0 * (Tt[4] + Te[8]  + ob0) + g1 * (Tt[6] + Te[10] + ob2);
            res.y = g0 * (Tt[5] + Te[9]  + ob1) + g1 * (Tt[7] + Te[11] + ob3);
        }
        {
            const unsigned pe = g_pairidx[q0 + 1];
            const float* Tt = Tb + (pe & 255) * 12;
            const float* Te = Tb + (pe >> 8) * 12;
            float g0 = Tt[0] + Te[2] + gb0;
            float g1 = Tt[1] + Te[3] + gb1;
            res.z = g0 * (Tt[4] + Te[8]  + ob0) + g1 * (Tt[6] + Te[10] + ob2);
            res.w = g0 * (Tt[5] + Te[9]  + ob1) + g1 * (Tt[7] + Te[11] + ob3);
        }
        const size_t p0 = (size_t)b * PAIRS_PER_B + q0;   // even
        *(float4*)(out_cause + p0 * 2) = res;
    }
}

// ---------------- launch ----------------
extern "C" void kernel_launch(void* const* d_in, const int* in_sizes, int n_in,
                              void* d_out, int out_size) {
    const float* pooled  = (const float*)d_in[0];
    const void*  spk     = d_in[1];
    const float* emo_w   = (const float*)d_in[2];
    const float* emo_b   = (const float*)d_in[3];
    const float* gate_w  = (const float*)d_in[4];
    const float* gate_b  = (const float*)d_in[5];
    const float* exp_w1  = (const float*)d_in[6];
    const float* exp_b1  = (const float*)d_in[7];
    const float* exp_w2  = (const float*)d_in[8];
    const float* exp_b2  = (const float*)d_in[9];
    float* out = (float*)d_out;

    prep_kernel<<<411, 256>>>(spk, emo_w, gate_w, exp_w1, exp_b1, exp_w2, exp_b2, pooled);
    solve_kernel<<<128, 256>>>(pooled, emo_b, gate_b, out, out + ROWS * NE);
}

// round 17
// speedup vs baseline: 1.0114x; 1.0114x over previous
#include <cuda_runtime.h>
#include <cstdint>

// ---------------- problem constants ----------------
#define BB   16
#define DD   64
#define HH   768
#define NE   7
#define ROWS (BB*DD)                 // 1024 utterances
#define PAIRS_PER_B (DD*(DD+1)/2)    // 2080
#define NPAIR (BB*PAIRS_PER_B)       // 33280
#define FOLD_TASKS (2*1552)          // 3104
#define LUT_W  65                    // pair-LUT warps
#define PF_W   96                    // pooled-prefetch warps
#define PACK_ELEMS (8480 + HH)       // 9248: emo+G1+G2+gate-tail+zero-pad row

// ---------------- device scratch (no allocs allowed) ----------------
__device__ float g_Ob[4];             // folded expert bias [e*2+c]
__device__ float g_W19[20*HH];        // SoA packed weights [m][j], m=19 is a ZERO pad row
__device__ float g_Tail[12*8];        // tail weights for f=768..775: [m][f-768] over the 12 T columns
__device__ float g_T[ROWS*12];        // per-utterance table [G1(2) G2(2) O1(4) O2(4)]
__device__ float g_spk[ROWS];         // speaker ids as float
__device__ unsigned short g_pairidx[PAIRS_PER_B]; // packed (end<<8)|t per in-batch pair q
__device__ unsigned int g_cnt[BB];    // per-batch monotonic sync counters (never reset)

// ================= kernel A: fold + pack + spk + LUT + pooled L2 prefetch ===
__global__ void __launch_bounds__(256)
prep_kernel(const void*  __restrict__ spk_raw,
            const float* __restrict__ emo_w,
            const float* __restrict__ gate_w,
            const float* __restrict__ w1,
            const float* __restrict__ b1,
            const float* __restrict__ w2,
            const float* __restrict__ b2,
            const float* __restrict__ pooled) {
    const int gw   = (blockIdx.x * blockDim.x + threadIdx.x) >> 5;
    const int lane = threadIdx.x & 31;

    if (gw < FOLD_TASKS) {
        const int e = gw / 1552, j = gw - e * 1552;
        const float4* a4  = (const float4*)(w1 + ((size_t)(e * 1552 + j)) * 256);
        const float4* wb4 = (const float4*)(w2 + e * 512);
        float4 x0 = a4[lane];
        float4 x1 = a4[lane + 32];
        float4 p0 = wb4[2 * lane];
        float4 p1 = wb4[2 * lane + 1];
        float4 p2 = wb4[64 + 2 * lane];
        float4 p3 = wb4[65 + 2 * lane];
        float a0 = x0.x*p0.x + x0.y*p0.z + x0.z*p1.x + x0.w*p1.z
                 + x1.x*p2.x + x1.y*p2.z + x1.z*p3.x + x1.w*p3.z;
        float a1 = x0.x*p0.y + x0.y*p0.w + x0.z*p1.y + x0.w*p1.w
                 + x1.x*p2.y + x1.y*p2.w + x1.z*p3.y + x1.w*p3.w;
        #pragma unroll
        for (int off = 16; off; off >>= 1) {
            a0 += __shfl_down_sync(0xffffffffu, a0, off);
            a1 += __shfl_down_sync(0xffffffffu, a1, off);
        }
        if (lane == 0) {
            if (j < HH) {                          // first-half feature -> O1 (m = 11+e*2+c)
                g_W19[(11 + e * 2) * HH + j] = a0;
                g_W19[(12 + e * 2) * HH + j] = a1;
            } else if (j < 776) {                  // tail O1 feature: Tail m = 4+e*2+c
                g_Tail[(4 + e * 2) * 8 + (j - HH)] = a0;
                g_Tail[(5 + e * 2) * 8 + (j - HH)] = a1;
            } else if (j < 776 + HH) {             // second-half feature -> O2 (m = 15+e*2+c)
                int jj = j - 776;
                g_W19[(15 + e * 2) * HH + jj] = a0;
                g_W19[(16 + e * 2) * HH + jj] = a1;
            } else {                               // tail O2 feature: Tail m = 8+e*2+c
                g_Tail[(8 + e * 2) * 8 + (j - 776 - HH)] = a0;
                g_Tail[(9 + e * 2) * 8 + (j - 776 - HH)] = a1;
            }
        }
    } else if (gw < FOLD_TASKS + 4) {
        const int idx = gw - FOLD_TASKS;          // 0..3
        const int e = idx >> 1, c = idx & 1;
        float s = 0.f;
        for (int k = lane; k < 256; k += 32)
            s += b1[e * 256 + k] * w2[e * 512 + k * 2 + c];
        #pragma unroll
        for (int off = 16; off; off >>= 1)
            s += __shfl_down_sync(0xffffffffu, s, off);
        if (lane == 0) g_Ob[idx] = s + b2[e * 2 + c];
    } else if (gw == FOLD_TASKS + 4) {
        // speaker_ids stored int64 or int32 (values in {0,1}).
        // int64: odd 32-bit words of first 1024 words are all zero.
        const unsigned int* u = (const unsigned int*)spk_raw;
        unsigned nz = 0;
        for (int i = lane; i < ROWS; i += 32) nz |= u[2 * i + 1];
        unsigned any = __ballot_sync(0xffffffffu, nz != 0u);
        const bool w64 = (any == 0u);
        for (int i = lane; i < ROWS; i += 32)
            g_spk[i] = (float)(w64 ? u[2 * i] : u[i]);
    } else if (gw < FOLD_TASKS + 16) {
        // pack emo (5376) + G1 (1536) + G2 (1536) + gate tail (32)
        //    + zero pad row m=19 (768) = 9248 elems  (exact bound: OOB guard)
        const int pid = gw - (FOLD_TASKS + 5);    // 0..10
        for (int idx = pid * 32 + lane; idx < PACK_ELEMS; idx += 11 * 32) {
            if (idx < 5376) {
                int c = idx / HH, j = idx - c * HH;       // m = c
                g_W19[c * HH + j] = emo_w[j * 7 + c];
            } else if (idx < 5376 + 1536) {
                int q = idx - 5376;
                int c = q / HH, j = q - c * HH;           // m = 7+c
                g_W19[(7 + c) * HH + j] = gate_w[j * 2 + c];
            } else if (idx < 5376 + 3072) {
                int q = idx - 5376 - 1536;
                int c = q / HH, j = q - c * HH;           // m = 9+c
                g_W19[(9 + c) * HH + j] = gate_w[(776 + j) * 2 + c];
            } else if (idx < 5376 + 3072 + 32) {
                int q = idx - 5376 - 3072;                // 0..31
                int m = q >> 3, f8 = q & 7;
                int f = HH + f8;
                float v = (m < 2) ? gate_w[f * 2 + m]
                                  : gate_w[(776 + f) * 2 + (m - 2)];
                g_Tail[m * 8 + f8] = v;
            } else {
                int j = idx - 8480;                       // 0..767: zero pad row
                g_W19[19 * HH + j] = 0.f;
            }
        }
    } else if (gw < FOLD_TASKS + 16 + LUT_W) {
        // pair index LUT: q -> (end, t), end-major tril order
        const int q = (gw - (FOLD_TASKS + 16)) * 32 + lane;
        if (q < PAIRS_PER_B) {
            int end = (int)((sqrtf(8.f * (float)q + 1.f) - 1.f) * 0.5f);
            while ((end + 1) * (end + 2) / 2 <= q) end++;
            while (end * (end + 1) / 2 > q) end--;
            int t = q - end * (end + 1) / 2;
            g_pairidx[q] = (unsigned short)((end << 8) | t);
        }
    } else if (gw < FOLD_TASKS + 16 + LUT_W + PF_W) {
        // L2-prefetch the 3MB pooled matrix so solve's x staging hits L2.
        const int pw = gw - (FOLD_TASKS + 16 + LUT_W);    // 0..95
        const int lg = pw * 32 + lane;                    // 0..3071
        #pragma unroll
        for (int it = 0; it < 8; it++) {
            const float* addr = pooled + (size_t)(lg + 3072 * it) * 32; // 128B lines
            asm volatile("prefetch.global.L2 [%0];" :: "l"(addr));
        }
    }
}

// ================= kernel B: 4-row weight reuse + smem-x + pairs ============
// grid 128 x 256: block = 8 contiguous rows, x staged to smem (24KB).
// Warp w = (row-quad rq = w>>2, m-group mg = w&3; m in [mg*5, mg*5+5)),
// m=19 is a zero pad row -> NO conditionals in the hot loop.
__global__ void __launch_bounds__(256, 2)
solve_kernel(const float* __restrict__ pooled,
             const float* __restrict__ emo_b,
             const float* __restrict__ gate_b,
             float* __restrict__ out_emo,     // [1024*7]
             float* __restrict__ out_cause) { // [33280*2]
    __shared__ float4 sx[8 * 192];            // 8 rows x 192 float4 = 24KB
    __shared__ float  spacc[8][20];           // [row_in_block][m] final sums

    const int tid  = threadIdx.x;
    const int lane = tid & 31;
    const int warp = tid >> 5;
    const int base = blockIdx.x * 8;          // first row of this block
    const int b    = blockIdx.x >> 3;         // batch
    const int s    = blockIdx.x & 7;          // pair slice

    // ---- stage x: 8 contiguous rows = 1536 float4, linear copy (L2 hits) ---
    {
        const float4* p4 = (const float4*)pooled + (size_t)base * 192;
        #pragma unroll 6
        for (int idx = tid; idx < 1536; idx += 256)
            sx[idx] = p4[idx];
    }
    __syncthreads();

    // ---- accumulate: warp = (row-quad, m-group), weights reused x4 rows ----
    {
        const int rq = warp >> 2;             // 0..1
        const int mg = warp & 3;              // 0..3
        const int m0 = mg * 5;
        const float4* gW4 = (const float4*)g_W19;

        float acc[4][5];
        #pragma unroll
        for (int rr = 0; rr < 4; rr++)
            #pragma unroll
            for (int mm = 0; mm < 5; mm++) acc[rr][mm] = 0.f;

        #pragma unroll
        for (int u = 0; u < 6; u++) {
            const int k = u * 32 + lane;      // float4 index 0..191
            float4 w[5];
            #pragma unroll
            for (int mm = 0; mm < 5; mm++)
                w[mm] = __ldg(gW4 + (m0 + mm) * 192 + k);
            #pragma unroll
            for (int rr = 0; rr < 4; rr++) {
                const float4 xv = sx[(rq * 4 + rr) * 192 + k];
                #pragma unroll
                for (int mm = 0; mm < 5; mm++)
                    acc[rr][mm] += xv.x * w[mm].x + xv.y * w[mm].y
                                 + xv.z * w[mm].z + xv.w * w[mm].w;
            }
        }

        // reduce 20 sums across the warp
        #pragma unroll
        for (int off = 16; off; off >>= 1) {
            #pragma unroll
            for (int rr = 0; rr < 4; rr++)
                #pragma unroll
                for (int mm = 0; mm < 5; mm++)
                    acc[rr][mm] += __shfl_down_sync(0xffffffffu, acc[rr][mm], off);
        }
        if (lane == 0) {
            #pragma unroll
            for (int rr = 0; rr < 4; rr++)
                #pragma unroll
                for (int mm = 0; mm < 5; mm++)
                    spacc[rq * 4 + rr][m0 + mm] = acc[rr][mm];
        }
    }
    __syncthreads();

    // ---- finalize: warps 0-7, one row each, lanes = m (sums final) ----
    {
        const int row = warp;                 // 0..7
        const int i = base + row;
        float sacc = (lane < 19) ? spacc[row][lane] : 0.f;
        float ep = (lane < 7) ? sacc + emo_b[lane] : 0.f;

        // convergent broadcasts (all 32 lanes execute the same shfls)
        float epv[7];
        #pragma unroll
        for (int f8 = 0; f8 < 7; f8++)
            epv[f8] = __shfl_sync(0xffffffffu, ep, f8);

        if (lane < 7)
            out_emo[(size_t)i * 7 + lane] = ep;
        else if (lane < 19) {
            const int m = lane - 7;           // T column 0..11
            float v = sacc;
            #pragma unroll
            for (int f8 = 0; f8 < 7; f8++)
                v += epv[f8] * g_Tail[m * 8 + f8];
            v += g_spk[i] * g_Tail[m * 8 + 7];
            g_T[i * 12 + m] = v;
        }
    }

    // ---- per-batch sync (monotonic ticket; 8 blocks per counter) ----
    // 128 blocks <= 148 SMs -> entire grid wave-1 resident, spin is safe.
    __syncthreads();
    if (tid == 0) {
        __threadfence();
        unsigned t = atomicAdd(&g_cnt[b], 1u) + 1u;
        unsigned round_end = ((t + 7u) / 8u) * 8u;
        volatile unsigned int* c = &g_cnt[b];
        while (*c < round_end) { __nanosleep(32); }
        __threadfence();
    }
    __syncthreads();

    // ---- pair phase: 260 pairs per block, 2 pairs/thread, float4 stores ----
    if (tid < 130) {
        const float gb0 = gate_b[0];
        const float gb1 = gate_b[1];
        const float ob0 = g_Ob[0], ob1 = g_Ob[1], ob2 = g_Ob[2], ob3 = g_Ob[3];
        const float* Tb = g_T + b * DD * 12;

        const int q0 = s * 260 + tid * 2;     // even; q0,q0+1 within batch
        float4 res;
        {
            const unsigned pe = g_pairidx[q0];
            const float* Tt = Tb + (pe & 255) * 12;
            const float* Te = Tb + (pe >> 8) * 12;
            float g0 = Tt[0] + Te[2] + gb0;
            float g1 = Tt[1] + Te[3] + gb1;
            res.x = g0 * (Tt[4] + Te[8]  + ob0) + g1 * (Tt[6] + Te[10] + ob2);
            res.y = g0 * (Tt[5] + Te[9]  + ob1) + g1 * (Tt[7] + Te[11] + ob3);
        }
        {
            const unsigned pe = g_pairidx[q0 + 1];
            const float* Tt = Tb + (pe & 255) * 12;
            const float* Te = Tb + (pe >> 8) * 12;
            float g0 = Tt[0] + Te[2] + gb0;
            float g1 = Tt[1] + Te[3] + gb1;
            res.z = g0 * (Tt[4] + Te[8]  + ob0) + g1 * (Tt[6] + Te[10] + ob2);
            res.w = g0 * (Tt[5] + Te[9]  + ob1) + g1 * (Tt[7] + Te[11] + ob3);
        }
        const size_t p0 = (size_t)b * PAIRS_PER_B + q0;   // even
        *(float4*)(out_cause + p0 * 2) = res;
    }
}

// ---------------- launch ----------------
extern "C" void kernel_launch(void* const* d_in, const int* in_sizes, int n_in,
                              void* d_out, int out_size) {
    const float* pooled  = (const float*)d_in[0];
    const void*  spk     = d_in[1];
    const float* emo_w   = (const float*)d_in[2];
    const float* emo_b   = (const float*)d_in[3];
    const float* gate_w  = (const float*)d_in[4];
    const float* gate_b  = (const float*)d_in[5];
    const float* exp_w1  = (const float*)d_in[6];
    const float* exp_b1  = (const float*)d_in[7];
    const float* exp_w2  = (const float*)d_in[8];
    const float* exp_b2  = (const float*)d_in[9];
    float* out = (float*)d_out;

    prep_kernel<<<411, 256>>>(spk, emo_w, gate_w, exp_w1, exp_b1, exp_w2, exp_b2, pooled);
    solve_kernel<<<128, 256>>>(pooled, emo_b, gate_b, out, out + ROWS * NE);
}